// round 6
// baseline (speedup 1.0000x reference)
#include <cuda_runtime.h>
#include <cuda_bf16.h>
#include <cstdint>

// ---------------------------------------------------------------------------
// RNN: h_t = tanh(x_t @ Wx + h_{t-1} @ Wh),  B=32, L=512, D=1024, fp32.
// Phase 1: xp = x @ Wx in-place into d_out. 128x128 tile, 8x8/thread, f32x2.
// Phase 2: persistent kernel, 512 threads/block, 4 independent group barriers,
//          Wh in registers (2 cols x 32 k per thread), xp prefetch.
// ---------------------------------------------------------------------------

#define B_DIM 32
#define L_DIM 512
#define D_DIM 1024
#define NB 128
#define TPB2 512

#define HROW_F 1152            // staged row: 32 chunks * (32 floats + 4 pad)
#define PART_STRIDE 36
#define HS_FLOATS (8 * HROW_F)
#define PART_OFF HS_FLOATS
#define PART_FLOATS (8 * 32 * PART_STRIDE)
#define SMEM2_FLOATS (PART_OFF + PART_FLOATS)

typedef unsigned long long u64;

__device__ unsigned g_ctrs[4];

__global__ void init_flags_kernel() {
    if (threadIdx.x < 4) g_ctrs[threadIdx.x] = 0u;
}

__device__ __forceinline__ u64 pack2(float lo, float hi) {
    u64 r;
    asm("mov.b64 %0, {%1, %2};" : "=l"(r) : "f"(lo), "f"(hi));
    return r;
}
__device__ __forceinline__ void unpack2(u64 v, float& lo, float& hi) {
    asm("mov.b64 {%0, %1}, %2;" : "=f"(lo), "=f"(hi) : "l"(v));
}
__device__ __forceinline__ void ffma2(u64& d, u64 a, u64 b) {
    asm("fma.rn.f32x2 %0, %1, %2, %0;" : "+l"(d) : "l"(a), "l"(b));
}

// ---------------------------------------------------------------------------
// Phase 1: C[16384,1024] = A[16384,1024] * W[1024,1024]
// 128x128 block tile, BK=16, 256 threads, 8x8 per thread, f32x2 FMAs.
// Double-buffered dynamic SMEM (A splatted as u64), register prefetch.
// ---------------------------------------------------------------------------
#define P1_AST 128             // u64 stride per k-row (even -> aligned)
#define P1_AS_U64 (16 * P1_AST)            // per buffer
#define P1_BS_F   (16 * 128)               // per buffer
#define P1_SMEM_BYTES (2 * P1_AS_U64 * 8 + 2 * P1_BS_F * 4)

__global__ __launch_bounds__(256) void gemm_xw_kernel(
    const float* __restrict__ A, const float* __restrict__ W,
    float* __restrict__ C)
{
    extern __shared__ __align__(16) unsigned char p1smem[];
    u64*   AsBuf = (u64*)p1smem;                               // [2][16*128]
    float* BsBuf = (float*)(p1smem + 2 * P1_AS_U64 * 8);       // [2][16*128]

    const int tid = threadIdx.x;
    const int m0 = blockIdx.y * 128;
    const int n0 = blockIdx.x * 128;

    const int aRow = tid >> 1;           // 0..127
    const int aHalf = (tid & 1) << 3;    // 0 or 8 (k offset)
    const int bRow = tid >> 4;           // 0..15
    const int bCol = (tid & 15) << 3;    // 0..120

    const int ty = tid >> 4;             // 0..15 -> m = ty*8
    const int tx = tid & 15;             // 0..15 -> n = tx*8

    const float* aPtr = A + (size_t)(m0 + aRow) * D_DIM + aHalf;
    const float* bPtr = W + (size_t)bRow * D_DIM + n0 + bCol;

    u64 acc[8][4];
#pragma unroll
    for (int m = 0; m < 8; ++m)
#pragma unroll
        for (int p = 0; p < 4; ++p) acc[m][p] = 0ull;

    // prologue: tile 0 into buffer 0
    {
        float4 a0 = *(const float4*)(aPtr);
        float4 a1 = *(const float4*)(aPtr + 4);
        float4 b0 = *(const float4*)(bPtr);
        float4 b1 = *(const float4*)(bPtr + 4);
        u64* as = AsBuf;
        as[(aHalf + 0) * P1_AST + aRow] = pack2(a0.x, a0.x);
        as[(aHalf + 1) * P1_AST + aRow] = pack2(a0.y, a0.y);
        as[(aHalf + 2) * P1_AST + aRow] = pack2(a0.z, a0.z);
        as[(aHalf + 3) * P1_AST + aRow] = pack2(a0.w, a0.w);
        as[(aHalf + 4) * P1_AST + aRow] = pack2(a1.x, a1.x);
        as[(aHalf + 5) * P1_AST + aRow] = pack2(a1.y, a1.y);
        as[(aHalf + 6) * P1_AST + aRow] = pack2(a1.z, a1.z);
        as[(aHalf + 7) * P1_AST + aRow] = pack2(a1.w, a1.w);
        float* bs = BsBuf;
        *(float4*)&bs[bRow * 128 + bCol]     = b0;
        *(float4*)&bs[bRow * 128 + bCol + 4] = b1;
    }
    __syncthreads();

    int cur = 0;
    for (int k0 = 0; k0 < D_DIM; k0 += 16) {
        float4 na0, na1, nb0, nb1;
        const bool more = (k0 + 16) < D_DIM;
        if (more) {
            na0 = *(const float4*)(aPtr + k0 + 16);
            na1 = *(const float4*)(aPtr + k0 + 20);
            nb0 = *(const float4*)(bPtr + (size_t)(k0 + 16) * D_DIM);
            nb1 = *(const float4*)(bPtr + (size_t)(k0 + 16) * D_DIM + 4);
        }

        const u64*   asb = AsBuf + cur * P1_AS_U64;
        const float* bsb = BsBuf + cur * P1_BS_F;
#pragma unroll
        for (int kk = 0; kk < 16; ++kk) {
            const ulonglong2* ap = (const ulonglong2*)(asb + kk * P1_AST + ty * 8);
            ulonglong2 t0 = ap[0];
            ulonglong2 t1 = ap[1];
            ulonglong2 t2 = ap[2];
            ulonglong2 t3 = ap[3];
            ulonglong2 bp0 = *(const ulonglong2*)(bsb + kk * 128 + tx * 8);
            ulonglong2 bp1 = *(const ulonglong2*)(bsb + kk * 128 + tx * 8 + 4);
            u64 a[8] = {t0.x, t0.y, t1.x, t1.y, t2.x, t2.y, t3.x, t3.y};
#pragma unroll
            for (int m = 0; m < 8; ++m) {
                ffma2(acc[m][0], a[m], bp0.x);
                ffma2(acc[m][1], a[m], bp0.y);
                ffma2(acc[m][2], a[m], bp1.x);
                ffma2(acc[m][3], a[m], bp1.y);
            }
        }

        if (more) {
            u64* as = AsBuf + (cur ^ 1) * P1_AS_U64;
            as[(aHalf + 0) * P1_AST + aRow] = pack2(na0.x, na0.x);
            as[(aHalf + 1) * P1_AST + aRow] = pack2(na0.y, na0.y);
            as[(aHalf + 2) * P1_AST + aRow] = pack2(na0.z, na0.z);
            as[(aHalf + 3) * P1_AST + aRow] = pack2(na0.w, na0.w);
            as[(aHalf + 4) * P1_AST + aRow] = pack2(na1.x, na1.x);
            as[(aHalf + 5) * P1_AST + aRow] = pack2(na1.y, na1.y);
            as[(aHalf + 6) * P1_AST + aRow] = pack2(na1.z, na1.z);
            as[(aHalf + 7) * P1_AST + aRow] = pack2(na1.w, na1.w);
            float* bs = BsBuf + (cur ^ 1) * P1_BS_F;
            *(float4*)&bs[bRow * 128 + bCol]     = nb0;
            *(float4*)&bs[bRow * 128 + bCol + 4] = nb1;
            __syncthreads();
        }
        cur ^= 1;
    }

#pragma unroll
    for (int m = 0; m < 8; ++m) {
        float4 v0, v1;
        unpack2(acc[m][0], v0.x, v0.y);
        unpack2(acc[m][1], v0.z, v0.w);
        unpack2(acc[m][2], v1.x, v1.y);
        unpack2(acc[m][3], v1.z, v1.w);
        float* cp = C + (size_t)(m0 + ty * 8 + m) * D_DIM + n0 + tx * 8;
        *(float4*)(cp)     = v0;
        *(float4*)(cp + 4) = v1;
    }
}

// ---------------------------------------------------------------------------
// Phase 2: persistent recurrence, 512 threads.
// bid -> (bq = bid>>5 owns b in [bq*8, bq*8+8), jg = bid&31 owns 32 columns).
// Thread: jq = lane&15 -> 2 columns; kc = warp*2 + (lane>>4) -> 32 k.
// Staging: warp w stages half-row (rw = w>>1, half = w&1).
// Reduce/out: threads 0..255 (b = tid>>5, j = tid&31).
// ---------------------------------------------------------------------------
__global__ __launch_bounds__(TPB2, 1) void rnn_steps_kernel(
    float* __restrict__ out,          // [B, L, D]: holds xp, overwritten by h
    const float* __restrict__ h0,     // [B, D]
    const float* __restrict__ Wh)     // [D, D]
{
    extern __shared__ __align__(16) float smem[];
    float* hs   = smem;               // 8 rows * HROW_F
    float* part = smem + PART_OFF;    // [8*32][36]

    const int tid  = threadIdx.x;
    const int warp = tid >> 5;
    const int lane = tid & 31;
    const int bid  = blockIdx.x;
    const int jg = bid & 31, bq = bid >> 5;
    const int j0 = jg * 32, b0 = bq * 8;
    const int jq = lane & 15;                   // column group (2 cols)
    const int kc = (warp << 1) | (lane >> 4);   // k-chunk 0..31
    const int kb = kc * 32;
    const int rw = warp >> 1, hf = warp & 1;    // staging row / half

    // Wh registers: wreg[jl][kk] packs Wh[kb+2kk][jcol], Wh[kb+2kk+1][jcol]
    u64 wreg[2][16];
#pragma unroll
    for (int jl = 0; jl < 2; ++jl) {
        const int jcol = j0 + jq * 2 + jl;
#pragma unroll
        for (int kk = 0; kk < 16; ++kk) {
            float w0 = Wh[(size_t)(kb + 2 * kk)     * D_DIM + jcol];
            float w1 = Wh[(size_t)(kb + 2 * kk + 1) * D_DIM + jcol];
            wreg[jl][kk] = pack2(w0, w1);
        }
    }

    unsigned* ctr = &g_ctrs[bq];
    // output ownership (threads 0..255): b = warp (0..7), j = lane
    const size_t obase = ((size_t)(b0 + warp) * L_DIM) * D_DIM + j0 + lane;

    float xp = (tid < 256) ? out[obase] : 0.0f;

    for (int t = 0; t < L_DIM; ++t) {
        // ---- stage h_{t-1}: warp w stages half-row (512 floats) ----
        const float* src = (t == 0)
            ? (h0 + (size_t)(b0 + rw) * D_DIM)
            : (out + ((size_t)(b0 + rw) * L_DIM + (t - 1)) * D_DIM);
        {
            float4 v[4];
#pragma unroll
            for (int m = 0; m < 4; ++m) {
                int idx4 = hf * 128 + m * 32 + lane;
                v[m] = __ldcg((const float4*)(src + idx4 * 4));
            }
#pragma unroll
            for (int m = 0; m < 4; ++m) {
                int idx4 = hf * 128 + m * 32 + lane;
                *(float4*)(hs + rw * HROW_F + (idx4 >> 3) * 36 + (idx4 & 7) * 4) = v[m];
            }
        }
        __syncthreads();

        // ---- compute: 8 b x 2 j x 32 k per thread (256 ffma2) ----
        u64 acc[8][2];
#pragma unroll
        for (int b = 0; b < 8; ++b) { acc[b][0] = 0ull; acc[b][1] = 0ull; }

#pragma unroll
        for (int b = 0; b < 8; ++b) {
            const ulonglong2* hb = (const ulonglong2*)(hs + b * HROW_F + kc * 36);
#pragma unroll
            for (int i = 0; i < 8; ++i) {
                ulonglong2 hp = hb[i];
                ffma2(acc[b][0], hp.x, wreg[0][2 * i]);
                ffma2(acc[b][1], hp.x, wreg[1][2 * i]);
                ffma2(acc[b][0], hp.y, wreg[0][2 * i + 1]);
                ffma2(acc[b][1], hp.y, wreg[1][2 * i + 1]);
            }
        }

        // ---- fold accumulators, store partials ----
#pragma unroll
        for (int b = 0; b < 8; ++b)
#pragma unroll
            for (int jl = 0; jl < 2; ++jl) {
                float lo, hi;
                unpack2(acc[b][jl], lo, hi);
                part[(b * 32 + jq * 2 + jl) * PART_STRIDE + kc] = lo + hi;
            }

        // prefetch xp for step t+1 (slot written only by this thread at t+1)
        float xp_next = 0.0f;
        if (tid < 256 && t + 1 < L_DIM) xp_next = out[obase + (size_t)(t + 1) * D_DIM];

        __syncthreads();

        // ---- final reduce (threads 0..255) + tanh + store ----
        if (tid < 256) {
            float s = xp;
            const float* pr = part + (warp * 32 + lane) * PART_STRIDE;
#pragma unroll
            for (int g = 0; g < 8; ++g) {
                float4 p = *(const float4*)(pr + g * 4);
                s += (p.x + p.y) + (p.z + p.w);
            }
            out[obase + (size_t)t * D_DIM] = tanhf(s);
        }

        // ---- group barrier: counter arrive + single-thread acquire poll ----
        __syncthreads();   // all STG issued; also protects hs/part reuse
        if (tid == 0) {
            asm volatile("red.release.gpu.add.u32 [%0], 1;" :: "l"(ctr) : "memory");
            const unsigned target = 32u * (unsigned)(t + 1);
            unsigned v;
            int spins = 0;
            while (true) {
                asm volatile("ld.acquire.gpu.u32 %0, [%1];" : "=r"(v) : "l"(ctr) : "memory");
                if (v >= target) break;
                if (++spins > 2) __nanosleep(32);
            }
        }
        __syncthreads();

        xp = xp_next;
    }
}

// ---------------------------------------------------------------------------
extern "C" void kernel_launch(void* const* d_in, const int* in_sizes, int n_in,
                              void* d_out, int out_size)
{
    (void)in_sizes; (void)n_in; (void)out_size;
    const float* x  = (const float*)d_in[0];
    const float* h0 = (const float*)d_in[1];
    const float* Wx = (const float*)d_in[2];
    const float* Wh = (const float*)d_in[3];
    float* out = (float*)d_out;

    cudaFuncSetAttribute(gemm_xw_kernel,
                         cudaFuncAttributeMaxDynamicSharedMemorySize,
                         P1_SMEM_BYTES);
    dim3 g1(D_DIM / 128, (B_DIM * L_DIM) / 128);
    gemm_xw_kernel<<<g1, 256, P1_SMEM_BYTES>>>(x, Wx, out);

    init_flags_kernel<<<1, 32>>>();
    size_t smem_bytes = (size_t)SMEM2_FLOATS * sizeof(float);
    cudaFuncSetAttribute(rnn_steps_kernel,
                         cudaFuncAttributeMaxDynamicSharedMemorySize,
                         (int)smem_bytes);
    rnn_steps_kernel<<<NB, TPB2, smem_bytes>>>(out, h0, Wh);
}

// round 9
// speedup vs baseline: 1.0698x; 1.0698x over previous
#include <cuda_runtime.h>
#include <cuda_bf16.h>
#include <cstdint>

// ---------------------------------------------------------------------------
// RNN: h_t = tanh(x_t @ Wx + h_{t-1} @ Wh),  B=32, L=512, D=1024, fp32.
// Phase 1: xp = x @ Wx via mma.sync 3xTF32 (hi/lo split) -> d_out.
// Phase 2: persistent recurrence (R5 design: 256 thr, Wh in regs, 4 group
//          barriers, xp prefetch).
// ---------------------------------------------------------------------------

#define B_DIM 32
#define L_DIM 512
#define D_DIM 1024
#define NB 128
#define TPB 256

typedef unsigned long long u64;

__device__ unsigned g_ctrs[4];

__global__ void init_flags_kernel() {
    if (threadIdx.x < 4) g_ctrs[threadIdx.x] = 0u;
}

__device__ __forceinline__ u64 pack2(float lo, float hi) {
    u64 r;
    asm("mov.b64 %0, {%1, %2};" : "=l"(r) : "f"(lo), "f"(hi));
    return r;
}
__device__ __forceinline__ void unpack2(u64 v, float& lo, float& hi) {
    asm("mov.b64 {%0, %1}, %2;" : "=f"(lo), "=f"(hi) : "l"(v));
}
__device__ __forceinline__ void ffma2(u64& d, u64 a, u64 b) {
    asm("fma.rn.f32x2 %0, %1, %2, %0;" : "+l"(d) : "l"(a), "l"(b));
}

// tf32 split: hi = tf32(v), lo = tf32(v - float(hi))
__device__ __forceinline__ void tf32_split(float v, uint32_t& hi, uint32_t& lo) {
    asm("cvt.rna.tf32.f32 %0, %1;" : "=r"(hi) : "f"(v));
    float r = v - __uint_as_float(hi);
    asm("cvt.rna.tf32.f32 %0, %1;" : "=r"(lo) : "f"(r));
}

__device__ __forceinline__ void mma_tf32(float* d, const uint32_t* a, const uint32_t* b) {
    asm("mma.sync.aligned.m16n8k8.row.col.f32.tf32.tf32.f32 "
        "{%0,%1,%2,%3}, {%4,%5,%6,%7}, {%8,%9}, {%0,%1,%2,%3};"
        : "+f"(d[0]), "+f"(d[1]), "+f"(d[2]), "+f"(d[3])
        : "r"(a[0]), "r"(a[1]), "r"(a[2]), "r"(a[3]), "r"(b[0]), "r"(b[1]));
}

// ---------------------------------------------------------------------------
// Phase 1: C[16384,1024] = A[16384,1024] * W[1024,1024], 3xTF32 mma.sync.
// Block tile 128x128, 8 warps (2 x 4), warp tile 64x32, K-tile 32,
// double-buffered fp32 SMEM (stride 36), register prefetch.
// ---------------------------------------------------------------------------
#define KT 32
#define AST 36                         // floats per row in SMEM tiles
#define BUF_F (128 * AST)              // one tile buffer (A or B)
#define P1_SMEM_BYTES (4 * BUF_F * 4)  // A0,A1,B0,B1

__global__ __launch_bounds__(256, 1) void gemm_mma_kernel(
    const float* __restrict__ A, const float* __restrict__ W,
    float* __restrict__ C)
{
    extern __shared__ __align__(16) float sm1[];
    float* As = sm1;                 // [2][128*36]  rows = m, cols = k
    float* Bs = sm1 + 2 * BUF_F;     // [2][128*36]  rows = n, cols = k

    const int tid  = threadIdx.x;
    const int warp = tid >> 5;
    const int lane = tid & 31;
    const int wm = warp >> 2;        // 0..1  -> m offset wm*64
    const int wn = warp & 3;         // 0..3  -> n offset wn*32
    const int m0 = blockIdx.y * 128;
    const int n0 = blockIdx.x * 128;

    const int lr = lane >> 2;        // 0..7
    const int lc = lane & 3;         // 0..3

    float acc[4][4][4];
#pragma unroll
    for (int i = 0; i < 4; ++i)
#pragma unroll
        for (int j = 0; j < 4; ++j)
#pragma unroll
            for (int p = 0; p < 4; ++p) acc[i][j][p] = 0.0f;

    // prologue: tile 0 into buffer 0
    {
#pragma unroll
        for (int it = 0; it < 4; ++it) {
            int idx = it * 256 + tid;
            int r = idx >> 3, k4 = idx & 7;
            float4 v = __ldg((const float4*)(A + (size_t)(m0 + r) * D_DIM + k4 * 4));
            *(float4*)(As + r * AST + k4 * 4) = v;
        }
#pragma unroll
        for (int it = 0; it < 4; ++it) {
            int idx = it * 256 + tid;
            int kr = idx >> 5, n4 = idx & 31;
            float4 v = __ldg((const float4*)(W + (size_t)kr * D_DIM + n0 + n4 * 4));
            float* bp = Bs + kr;
            bp[(n4 * 4 + 0) * AST] = v.x;
            bp[(n4 * 4 + 1) * AST] = v.y;
            bp[(n4 * 4 + 2) * AST] = v.z;
            bp[(n4 * 4 + 3) * AST] = v.w;
        }
    }
    __syncthreads();

    int cur = 0;
    for (int kt = 0; kt < D_DIM / KT; ++kt) {
        // prefetch next tile into registers
        float4 va[4], vb[4];
        const bool more = (kt + 1) < (D_DIM / KT);
        if (more) {
            const int k0n = (kt + 1) * KT;
#pragma unroll
            for (int it = 0; it < 4; ++it) {
                int idx = it * 256 + tid;
                int r = idx >> 3, k4 = idx & 7;
                va[it] = __ldg((const float4*)(A + (size_t)(m0 + r) * D_DIM + k0n + k4 * 4));
            }
#pragma unroll
            for (int it = 0; it < 4; ++it) {
                int idx = it * 256 + tid;
                int kr = idx >> 5, n4 = idx & 31;
                vb[it] = __ldg((const float4*)(W + (size_t)(k0n + kr) * D_DIM + n0 + n4 * 4));
            }
        }

        // compute on buffer cur
        const float* as = As + cur * BUF_F;
        const float* bs = Bs + cur * BUF_F;
#pragma unroll
        for (int ks = 0; ks < 4; ++ks) {
            const int kbase = ks * 8;
            // A fragments (4 m-frags), split hi/lo
            uint32_t ah[4][4], al[4][4];
#pragma unroll
            for (int fm = 0; fm < 4; ++fm) {
                const int rbase = wm * 64 + fm * 16;
                float a0 = as[(rbase + lr) * AST + kbase + lc];
                float a1 = as[(rbase + lr + 8) * AST + kbase + lc];
                float a2 = as[(rbase + lr) * AST + kbase + lc + 4];
                float a3 = as[(rbase + lr + 8) * AST + kbase + lc + 4];
                tf32_split(a0, ah[fm][0], al[fm][0]);
                tf32_split(a1, ah[fm][1], al[fm][1]);
                tf32_split(a2, ah[fm][2], al[fm][2]);
                tf32_split(a3, ah[fm][3], al[fm][3]);
            }
            // B fragments (4 n-frags), split hi/lo
            uint32_t bh[4][2], bl[4][2];
#pragma unroll
            for (int fn = 0; fn < 4; ++fn) {
                const int nbase = wn * 32 + fn * 8;
                float b0 = bs[(nbase + lr) * AST + kbase + lc];
                float b1 = bs[(nbase + lr) * AST + kbase + lc + 4];
                tf32_split(b0, bh[fn][0], bl[fn][0]);
                tf32_split(b1, bh[fn][1], bl[fn][1]);
            }
            // 3 products per (fm, fn)
#pragma unroll
            for (int fm = 0; fm < 4; ++fm)
#pragma unroll
                for (int fn = 0; fn < 4; ++fn) {
                    mma_tf32(acc[fm][fn], ah[fm], bl[fn]);
                    mma_tf32(acc[fm][fn], al[fm], bh[fn]);
                    mma_tf32(acc[fm][fn], ah[fm], bh[fn]);
                }
        }

        if (more) {
            float* asn = As + (cur ^ 1) * BUF_F;
            float* bsn = Bs + (cur ^ 1) * BUF_F;
#pragma unroll
            for (int it = 0; it < 4; ++it) {
                int idx = it * 256 + tid;
                int r = idx >> 3, k4 = idx & 7;
                *(float4*)(asn + r * AST + k4 * 4) = va[it];
            }
#pragma unroll
            for (int it = 0; it < 4; ++it) {
                int idx = it * 256 + tid;
                int kr = idx >> 5, n4 = idx & 31;
                float* bp = bsn + kr;
                bp[(n4 * 4 + 0) * AST] = vb[it].x;
                bp[(n4 * 4 + 1) * AST] = vb[it].y;
                bp[(n4 * 4 + 2) * AST] = vb[it].z;
                bp[(n4 * 4 + 3) * AST] = vb[it].w;
            }
            __syncthreads();
        }
        cur ^= 1;
    }

    // epilogue: store accumulators (float2 per frag-row)
#pragma unroll
    for (int fm = 0; fm < 4; ++fm) {
        const int rbase = m0 + wm * 64 + fm * 16 + lr;
#pragma unroll
        for (int fn = 0; fn < 4; ++fn) {
            const int cbase = n0 + wn * 32 + fn * 8 + lc * 2;
            *(float2*)(C + (size_t)rbase * D_DIM + cbase) =
                make_float2(acc[fm][fn][0], acc[fm][fn][1]);
            *(float2*)(C + (size_t)(rbase + 8) * D_DIM + cbase) =
                make_float2(acc[fm][fn][2], acc[fm][fn][3]);
        }
    }
}

// ---------------------------------------------------------------------------
// Phase 2: persistent recurrence (R5 design, 256 threads).
// bid -> (bq = bid>>5 owns b in [bq*8, bq*8+8), jg = bid&31 owns 32 columns).
// Thread: jq = lane&7 -> 4 columns; kc = warp*4 + (lane>>3) -> 32 k.
// ---------------------------------------------------------------------------
#define HROW_F 1152
#define PART_STRIDE 36
#define HS_FLOATS (8 * HROW_F)
#define PART_OFF HS_FLOATS
#define PART_FLOATS (8 * 32 * PART_STRIDE)
#define SMEM2_FLOATS (PART_OFF + PART_FLOATS)

__global__ __launch_bounds__(TPB, 1) void rnn_steps_kernel(
    float* __restrict__ out,          // [B, L, D]: holds xp, overwritten by h
    const float* __restrict__ h0,     // [B, D]
    const float* __restrict__ Wh)     // [D, D]
{
    extern __shared__ __align__(16) float smem[];
    float* hs   = smem;
    float* part = smem + PART_OFF;

    const int tid  = threadIdx.x;
    const int warp = tid >> 5;
    const int lane = tid & 31;
    const int bid  = blockIdx.x;
    const int jg = bid & 31, bq = bid >> 5;
    const int j0 = jg * 32, b0 = bq * 8;
    const int jq = lane & 7;
    const int kc = (warp << 2) | (lane >> 3);
    const int kb = kc * 32;

    u64 wreg[4][16];
#pragma unroll
    for (int jl = 0; jl < 4; ++jl) {
        const int jcol = j0 + jq * 4 + jl;
#pragma unroll
        for (int kk = 0; kk < 16; ++kk) {
            float w0 = Wh[(size_t)(kb + 2 * kk)     * D_DIM + jcol];
            float w1 = Wh[(size_t)(kb + 2 * kk + 1) * D_DIM + jcol];
            wreg[jl][kk] = pack2(w0, w1);
        }
    }

    unsigned* ctr = &g_ctrs[bq];
    const size_t obase = ((size_t)(b0 + warp) * L_DIM) * D_DIM + j0 + lane;

    float xp = out[obase];

    for (int t = 0; t < L_DIM; ++t) {
        const size_t orow = obase + (size_t)t * D_DIM;

        const float* src = (t == 0)
            ? (h0 + (size_t)(b0 + warp) * D_DIM)
            : (out + ((size_t)(b0 + warp) * L_DIM + (t - 1)) * D_DIM);
#pragma unroll
        for (int half = 0; half < 2; ++half) {
            float4 v[4];
#pragma unroll
            for (int m = 0; m < 4; ++m)
                v[m] = __ldcg((const float4*)(src + ((half * 4 + m) * 32 + lane) * 4));
#pragma unroll
            for (int m = 0; m < 4; ++m) {
                int idx = (half * 4 + m) * 32 + lane;
                *(float4*)(hs + warp * HROW_F + (idx >> 3) * 36 + (idx & 7) * 4) = v[m];
            }
        }
        __syncthreads();

        u64 acc[8][4];
#pragma unroll
        for (int b = 0; b < 8; ++b)
#pragma unroll
            for (int jl = 0; jl < 4; ++jl) acc[b][jl] = 0ull;

#pragma unroll
        for (int b = 0; b < 8; ++b) {
            const ulonglong2* hb = (const ulonglong2*)(hs + b * HROW_F + kc * 36);
#pragma unroll
            for (int i = 0; i < 8; ++i) {
                ulonglong2 hp = hb[i];
                ffma2(acc[b][0], hp.x, wreg[0][2 * i]);
                ffma2(acc[b][1], hp.x, wreg[1][2 * i]);
                ffma2(acc[b][2], hp.x, wreg[2][2 * i]);
                ffma2(acc[b][3], hp.x, wreg[3][2 * i]);
                ffma2(acc[b][0], hp.y, wreg[0][2 * i + 1]);
                ffma2(acc[b][1], hp.y, wreg[1][2 * i + 1]);
                ffma2(acc[b][2], hp.y, wreg[2][2 * i + 1]);
                ffma2(acc[b][3], hp.y, wreg[3][2 * i + 1]);
            }
        }

#pragma unroll
        for (int b = 0; b < 8; ++b)
#pragma unroll
            for (int jl = 0; jl < 4; ++jl) {
                float lo, hi;
                unpack2(acc[b][jl], lo, hi);
                part[(b * 32 + jq * 4 + jl) * PART_STRIDE + kc] = lo + hi;
            }

        float xp_next = 0.0f;
        if (t + 1 < L_DIM) xp_next = out[orow + D_DIM];

        __syncthreads();

        float s = xp;
        const float* pr = part + (warp * 32 + lane) * PART_STRIDE;
#pragma unroll
        for (int g = 0; g < 8; ++g) {
            float4 p = *(const float4*)(pr + g * 4);
            s += (p.x + p.y) + (p.z + p.w);
        }
        out[orow] = tanhf(s);

        __syncthreads();
        if (tid == 0) {
            asm volatile("red.release.gpu.add.u32 [%0], 1;" :: "l"(ctr) : "memory");
            const unsigned target = 32u * (unsigned)(t + 1);
            unsigned v;
            int spins = 0;
            while (true) {
                asm volatile("ld.acquire.gpu.u32 %0, [%1];" : "=r"(v) : "l"(ctr) : "memory");
                if (v >= target) break;
                if (++spins > 2) __nanosleep(32);
            }
        }
        __syncthreads();

        xp = xp_next;
    }
}

// ---------------------------------------------------------------------------
extern "C" void kernel_launch(void* const* d_in, const int* in_sizes, int n_in,
                              void* d_out, int out_size)
{
    (void)in_sizes; (void)n_in; (void)out_size;
    const float* x  = (const float*)d_in[0];
    const float* h0 = (const float*)d_in[1];
    const float* Wx = (const float*)d_in[2];
    const float* Wh = (const float*)d_in[3];
    float* out = (float*)d_out;

    // phase 1: 3xTF32 tensor-core GEMM
    cudaFuncSetAttribute(gemm_mma_kernel,
                         cudaFuncAttributeMaxDynamicSharedMemorySize,
                         P1_SMEM_BYTES);
    dim3 g1(D_DIM / 128, (B_DIM * L_DIM) / 128);
    gemm_mma_kernel<<<g1, 256, P1_SMEM_BYTES>>>(x, Wx, out);

    // phase 2: persistent recurrence
    init_flags_kernel<<<1, 32>>>();
    size_t smem_bytes = (size_t)SMEM2_FLOATS * sizeof(float);
    cudaFuncSetAttribute(rnn_steps_kernel,
                         cudaFuncAttributeMaxDynamicSharedMemorySize,
                         (int)smem_bytes);
    rnn_steps_kernel<<<NB, TPB, smem_bytes>>>(out, h0, Wh);
}